// round 12
// baseline (speedup 1.0000x reference)
#include <cuda_runtime.h>
#include <cuda_fp16.h>
#include <cstdint>

#define NN 100000
#define D  512

// Scratch (allocation-free rule: __device__ globals)
__device__ __align__(128) __half g_h[(size_t)NN * D];     // fp16 intermediate h
__device__ __align__(128) __half g_ahi[(size_t)NN * D];   // A operand for GEMM
__device__ __align__(128) __half g_w1[D * D], g_w2[D * D];
__device__ float g_rsd[NN];

static __device__ __forceinline__ uint32_t smem_u32(const void* p) {
    uint32_t a;
    asm("{ .reg .u64 t; cvta.to.shared.u64 t, %1; cvt.u32.u64 %0, t; }" : "=r"(a) : "l"(p));
    return a;
}

#define LDSM4(r, addr) \
    asm volatile("ldmatrix.sync.aligned.m8n8.x4.shared.b16 {%0,%1,%2,%3}, [%4];" \
        : "=r"((r)[0]), "=r"((r)[1]), "=r"((r)[2]), "=r"((r)[3]) : "r"(addr))

#define MMA16816(d, a, b0, b1) \
    asm volatile("mma.sync.aligned.m16n8k16.row.col.f32.f16.f16.f32 " \
        "{%0,%1,%2,%3}, {%4,%5,%6,%7}, {%8,%9}, {%0,%1,%2,%3};" \
        : "+f"((d)[0]), "+f"((d)[1]), "+f"((d)[2]), "+f"((d)[3]) \
        : "r"((a)[0]), "r"((a)[1]), "r"((a)[2]), "r"((a)[3]), "r"(b0), "r"(b1))

#define CP16(dst, src, n) \
    asm volatile("cp.async.cg.shared.global [%0], [%1], 16, %2;" \
        :: "r"(dst), "l"(src), "r"(n))
#define CP_COMMIT() asm volatile("cp.async.commit_group;" ::: "memory")
#define CP_WAIT1()  asm volatile("cp.async.wait_group 1;" ::: "memory")

__global__ void deg_kernel(const int* __restrict__ ei) {
    int i = blockIdx.x * blockDim.x + threadIdx.x;
    if (i >= NN) return;
    int c = 1;
#pragma unroll
    for (int j = 0; j < 3; j++) c += (ei[i * 3 + j] >= 0);
    g_rsd[i] = rsqrtf((float)c);
}

// fp32 -> fp16 (round-to-nearest)
__global__ void tohalf_kernel(const float* __restrict__ src,
                              __half* __restrict__ hi, int n4) {
    int i = blockIdx.x * blockDim.x + threadIdx.x;
    if (i >= n4) return;
    float4 v = ((const float4*)src)[i];
    __half2 a = __floats2half2_rn(v.x, v.y);
    __half2 b = __floats2half2_rn(v.z, v.w);
    ((uint2*)hi)[i] = make_uint2(*(uint32_t*)&a, *(uint32_t*)&b);
}

// ---------------- single-term fp16 HMMA GEMM ----------------
// 128x128 block, 4 warps of 64x64 tiles, 128 threads, 3-stage, 2 CTAs/SM.
// Stage (32KB): A[128 x 128B] @0, W @16K. Row r = 8 x 16B slots,
// slot s (k [8s..8s+8)) at phys slot s^(r&7).
static constexpr int STAGE_BYTES = 32768;
static constexpr int NSTAGE = 3;
static constexpr int SMEM_TOTAL  = 1024 + NSTAGE * STAGE_BYTES;

__global__ void __launch_bounds__(128, 2)
gemm_hmma(const __half* __restrict__ Ahi, const __half* __restrict__ W,
          const float* __restrict__ bias, __half* __restrict__ Ch) {
    extern __shared__ char smem[];
    const int tid = threadIdx.x, lid = tid & 31, wid = tid >> 5;
    const int m0 = blockIdx.y * 128, n0 = blockIdx.x * 128;

    float* biasS = (float*)smem;
    biasS[tid] = bias[n0 + tid];
    const uint32_t sb = smem_u32(smem) + 1024;

    // loader: 1 thread per row, 8 A-slots + 8 W-slots each
    const int r = tid;
    const bool aval = (m0 + r) < NN;
    const int pa = aval ? 16 : 0;
    const __half* aSrc = Ahi + (size_t)(m0 + (aval ? r : 0)) * D;
    const __half* bSrc = W   + (size_t)(n0 + r) * D;

    float acc[4][8][4];
#pragma unroll
    for (int mt = 0; mt < 4; mt++)
#pragma unroll
        for (int nt = 0; nt < 8; nt++)
#pragma unroll
            for (int j = 0; j < 4; j++) acc[mt][nt][j] = 0.f;

    auto issue = [&](int c) {
        const int st = c % NSTAGE;
        const uint32_t dA = sb + st * STAGE_BYTES + r * 128;
        const int ko = c * 64;
#pragma unroll
        for (int s = 0; s < 8; s++) {
            const uint32_t so = (uint32_t)((s ^ (r & 7)) << 4);
            CP16(dA + so,         aSrc + ko + s * 8, pa);
            CP16(dA + 16384 + so, bSrc + ko + s * 8, 16);
        }
    };

    // warp grid: 2 along M x 2 along N, 64x64 each
    const int mbase = (wid & 1) * 64, nbase = (wid >> 1) * 64;
    const int q = lid >> 3, rr = lid & 7;

    auto compute = [&](int st) {
        const uint32_t aT = sb + st * STAGE_BYTES;
        const uint32_t bT = aT + 16384;
#pragma unroll
        for (int ks = 0; ks < 4; ks++) {
            uint32_t ah[4][4];
#pragma unroll
            for (int mt = 0; mt < 4; mt++) {
                int row = mbase + mt * 16 + (q & 1) * 8 + rr;
                int ch  = 2 * ks + (q >> 1);
                LDSM4(ah[mt], aT + row * 128 + ((ch ^ (row & 7)) << 4));
            }
#pragma unroll
            for (int p = 0; p < 4; p++) {
                uint32_t bh[4];
                int nrow = nbase + p * 16 + (q >> 1) * 8 + rr;
                int ch   = 2 * ks + (q & 1);
                LDSM4(bh, bT + (uint32_t)(nrow * 128 + ((ch ^ (nrow & 7)) << 4)));
#pragma unroll
                for (int mt = 0; mt < 4; mt++)
#pragma unroll
                    for (int j = 0; j < 2; j++)
                        MMA16816(acc[mt][2 * p + j], ah[mt], bh[2 * j], bh[2 * j + 1]);
            }
        }
    };

    issue(0); CP_COMMIT();
    issue(1); CP_COMMIT();

#pragma unroll 1
    for (int c = 0; c < 8; c++) {
        CP_WAIT1();            // stage c resident
        __syncthreads();       // all warps done with stage (c-1)%3 reads
        if (c + 2 < 8) issue(c + 2);   // writes stage (c+2)%3 == (c-1)%3
        CP_COMMIT();           // uniform group count (may be empty)
        compute(c % NSTAGE);
    }

    // epilogue: half((acc + bias) * rsd)
#pragma unroll
    for (int mt = 0; mt < 4; mt++)
#pragma unroll
        for (int half = 0; half < 2; half++) {
            int row = m0 + mbase + mt * 16 + (lid >> 2) + half * 8;
            if (row < NN) {
                float rs = g_rsd[row];
#pragma unroll
                for (int nt = 0; nt < 8; nt++) {
                    int colrel = nbase + nt * 8 + (lid & 3) * 2;
                    __half2 hv = __floats2half2_rn(
                        (acc[mt][nt][half * 2 + 0] + biasS[colrel + 0]) * rs,
                        (acc[mt][nt][half * 2 + 1] + biasS[colrel + 1]) * rs);
                    *(uint32_t*)(Ch + (size_t)row * D + n0 + colrel) = *(uint32_t*)&hv;
                }
            }
        }
}

static __device__ __forceinline__ void addh4(float& a0, float& a1, float& a2, float& a3, uint2 v) {
    __half2 p = *reinterpret_cast<__half2*>(&v.x);
    __half2 q = *reinterpret_cast<__half2*>(&v.y);
    a0 += __low2float(p); a1 += __high2float(p);
    a2 += __low2float(q); a3 += __high2float(q);
}

__global__ void agg_half_kernel(const __half* __restrict__ h,
                                const int* __restrict__ ei,
                                __half* __restrict__ hi) {
    const size_t node = blockIdx.x;
    const int t = threadIdx.x;
    const uint2* hv = (const uint2*)h;

    float a0 = 0.f, a1 = 0.f, a2 = 0.f, a3 = 0.f;
    addh4(a0, a1, a2, a3, hv[node * 128 + t]);
    int e0 = ei[node * 3 + 0];
    int e1 = ei[node * 3 + 1];
    int e2 = ei[node * 3 + 2];
    if (e0 >= 0) addh4(a0, a1, a2, a3, hv[(size_t)e0 * 128 + t]);
    if (e1 >= 0) addh4(a0, a1, a2, a3, hv[(size_t)e1 * 128 + t]);
    if (e2 >= 0) addh4(a0, a1, a2, a3, hv[(size_t)e2 * 128 + t]);

    const float rs = g_rsd[node];
    a0 *= rs; a1 *= rs; a2 *= rs; a3 *= rs;
    a0 = a0 > 0.f ? a0 : expm1f(a0);
    a1 = a1 > 0.f ? a1 : expm1f(a1);
    a2 = a2 > 0.f ? a2 : expm1f(a2);
    a3 = a3 > 0.f ? a3 : expm1f(a3);

    __half2 p = __floats2half2_rn(a0, a1);
    __half2 q = __floats2half2_rn(a2, a3);
    ((uint2*)hi)[node * 128 + t] = make_uint2(*(uint32_t*)&p, *(uint32_t*)&q);
}

__global__ void agg_final_kernel(const __half* __restrict__ h,
                                 const int* __restrict__ ei,
                                 float* __restrict__ out) {
    const size_t node = blockIdx.x;
    const int t = threadIdx.x;
    const uint2* hv = (const uint2*)h;

    float a0 = 0.f, a1 = 0.f, a2 = 0.f, a3 = 0.f;
    addh4(a0, a1, a2, a3, hv[node * 128 + t]);
    int e0 = ei[node * 3 + 0];
    int e1 = ei[node * 3 + 1];
    int e2 = ei[node * 3 + 2];
    if (e0 >= 0) addh4(a0, a1, a2, a3, hv[(size_t)e0 * 128 + t]);
    if (e1 >= 0) addh4(a0, a1, a2, a3, hv[(size_t)e1 * 128 + t]);
    if (e2 >= 0) addh4(a0, a1, a2, a3, hv[(size_t)e2 * 128 + t]);

    const float rs = g_rsd[node];
    a0 *= rs; a1 *= rs; a2 *= rs; a3 *= rs;
    float4 o;
    o.x = a0 > 0.f ? a0 : expm1f(a0);
    o.y = a1 > 0.f ? a1 : expm1f(a1);
    o.z = a2 > 0.f ? a2 : expm1f(a2);
    o.w = a3 > 0.f ? a3 : expm1f(a3);
    ((float4*)out)[node * 128 + t] = o;
}

extern "C" void kernel_launch(void* const* d_in, const int* in_sizes, int n_in,
                              void* d_out, int out_size) {
    const float* x  = nullptr;
    const int*   ei = nullptr;
    const float* Wt[2] = {nullptr, nullptr};
    const float* bt[2] = {nullptr, nullptr};
    int wi = 0, bi = 0;
    for (int i = 0; i < n_in; i++) {
        int sz = in_sizes[i];
        if (sz == NN * D)      x = (const float*)d_in[i];
        else if (sz == NN * 3) ei = (const int*)d_in[i];
        else if (sz == D * D)  { if (wi < 2) Wt[wi++] = (const float*)d_in[i]; }
        else if (sz == D)      { if (bi < 2) bt[bi++] = (const float*)d_in[i]; }
    }
    float* out = (float*)d_out;

    void *ph, *pah, *pw1, *pw2;
    cudaGetSymbolAddress(&ph,  g_h);
    cudaGetSymbolAddress(&pah, g_ahi);
    cudaGetSymbolAddress(&pw1, g_w1);
    cudaGetSymbolAddress(&pw2, g_w2);
    __half* hbuf = (__half*)ph;
    __half* ahi = (__half*)pah;
    __half *w1 = (__half*)pw1, *w2 = (__half*)pw2;

    cudaFuncSetAttribute(gemm_hmma, cudaFuncAttributeMaxDynamicSharedMemorySize, SMEM_TOTAL);

    deg_kernel<<<(NN + 255) / 256, 256>>>(ei);
    tohalf_kernel<<<(NN * D / 4 + 255) / 256, 256>>>(x, ahi, NN * D / 4);
    tohalf_kernel<<<(D * D / 4 + 255) / 256, 256>>>(Wt[0], w1, D * D / 4);
    tohalf_kernel<<<(D * D / 4 + 255) / 256, 256>>>(Wt[1], w2, D * D / 4);

    dim3 ggrid(D / 128, (NN + 127) / 128);  // (4, 782)
    gemm_hmma<<<ggrid, 128, SMEM_TOTAL>>>(ahi, w1, bt[0], hbuf);
    agg_half_kernel<<<NN, 128>>>(hbuf, ei, ahi);
    gemm_hmma<<<ggrid, 128, SMEM_TOTAL>>>(ahi, w2, bt[1], hbuf);
    agg_final_kernel<<<NN, 128>>>(hbuf, ei, out);
}

// round 14
// speedup vs baseline: 1.2593x; 1.2593x over previous
#include <cuda_runtime.h>
#include <cuda_fp16.h>
#include <cstdint>

#define NN 100000
#define D  512

// Scratch (allocation-free rule: __device__ globals)
__device__ __align__(128) __half g_h[(size_t)NN * D];     // fp16 intermediate h
__device__ __align__(128) __half g_ahi[(size_t)NN * D];   // A operand for GEMM
__device__ __align__(128) __half g_w1[D * D], g_w2[D * D];
__device__ float g_rsd[NN];

static __device__ __forceinline__ uint32_t smem_u32(const void* p) {
    uint32_t a;
    asm("{ .reg .u64 t; cvta.to.shared.u64 t, %1; cvt.u32.u64 %0, t; }" : "=r"(a) : "l"(p));
    return a;
}

#define LDSM4(r, addr) \
    asm volatile("ldmatrix.sync.aligned.m8n8.x4.shared.b16 {%0,%1,%2,%3}, [%4];" \
        : "=r"((r)[0]), "=r"((r)[1]), "=r"((r)[2]), "=r"((r)[3]) : "r"(addr))

#define MMA16816(d, a, b0, b1) \
    asm volatile("mma.sync.aligned.m16n8k16.row.col.f32.f16.f16.f32 " \
        "{%0,%1,%2,%3}, {%4,%5,%6,%7}, {%8,%9}, {%0,%1,%2,%3};" \
        : "+f"((d)[0]), "+f"((d)[1]), "+f"((d)[2]), "+f"((d)[3]) \
        : "r"((a)[0]), "r"((a)[1]), "r"((a)[2]), "r"((a)[3]), "r"(b0), "r"(b1))

#define CP16(dst, src, n) \
    asm volatile("cp.async.cg.shared.global [%0], [%1], 16, %2;" \
        :: "r"(dst), "l"(src), "r"(n))
#define CP_COMMIT() asm volatile("cp.async.commit_group;" ::: "memory")
#define CP_WAIT1()  asm volatile("cp.async.wait_group 1;" ::: "memory")

__global__ void deg_kernel(const int* __restrict__ ei) {
    int i = blockIdx.x * blockDim.x + threadIdx.x;
    if (i >= NN) return;
    int c = 1;
#pragma unroll
    for (int j = 0; j < 3; j++) c += (ei[i * 3 + j] >= 0);
    g_rsd[i] = rsqrtf((float)c);
}

// fp32 -> fp16, 8 floats per thread (2x LDG.128 -> 1x STG.128)
__global__ void tohalf_kernel(const float* __restrict__ src,
                              __half* __restrict__ hi, int n8) {
    int i = blockIdx.x * blockDim.x + threadIdx.x;
    if (i >= n8) return;
    float4 v0 = ((const float4*)src)[2 * i];
    float4 v1 = ((const float4*)src)[2 * i + 1];
    __half2 a = __floats2half2_rn(v0.x, v0.y);
    __half2 b = __floats2half2_rn(v0.z, v0.w);
    __half2 c = __floats2half2_rn(v1.x, v1.y);
    __half2 d = __floats2half2_rn(v1.z, v1.w);
    ((uint4*)hi)[i] = make_uint4(*(uint32_t*)&a, *(uint32_t*)&b,
                                 *(uint32_t*)&c, *(uint32_t*)&d);
}

// ---------------- single-term fp16 HMMA GEMM (R11 config) ----------------
// 128x128 block, 8 warps of 64x32 tiles, 256 threads, 3-stage, 2 CTAs/SM.
// Stage (32KB): A[128 x 128B] @0, W @16K. Row r = 8 x 16B slots,
// slot s (k [8s..8s+8)) at phys slot s^(r&7).
static constexpr int STAGE_BYTES = 32768;
static constexpr int NSTAGE = 3;
static constexpr int SMEM_TOTAL  = 1024 + NSTAGE * STAGE_BYTES;

__global__ void __launch_bounds__(256, 2)
gemm_hmma(const __half* __restrict__ Ahi, const __half* __restrict__ W,
          const float* __restrict__ bias, __half* __restrict__ Ch) {
    extern __shared__ char smem[];
    const int tid = threadIdx.x, lid = tid & 31, wid = tid >> 5;
    const int m0 = blockIdx.y * 128, n0 = blockIdx.x * 128;

    float* biasS = (float*)smem;
    if (tid < 128) biasS[tid] = bias[n0 + tid];
    const uint32_t sb = smem_u32(smem) + 1024;

    const int r = tid >> 1, h = tid & 1;
    const bool aval = (m0 + r) < NN;
    const int pa = aval ? 16 : 0;
    const __half* aSrc = Ahi + (size_t)(m0 + (aval ? r : 0)) * D;
    const __half* bSrc = W   + (size_t)(n0 + r) * D;

    float acc[4][4][4];
#pragma unroll
    for (int mt = 0; mt < 4; mt++)
#pragma unroll
        for (int nt = 0; nt < 4; nt++)
#pragma unroll
            for (int j = 0; j < 4; j++) acc[mt][nt][j] = 0.f;

    auto issue = [&](int c) {
        const int st = c % NSTAGE;
        const uint32_t dA = sb + st * STAGE_BYTES + r * 128;
        const int ko = c * 64;
#pragma unroll
        for (int j = 0; j < 4; j++) {
            const int s = 4 * h + j;
            const uint32_t so = (uint32_t)((s ^ (r & 7)) << 4);
            CP16(dA + so,         aSrc + ko + s * 8, pa);
            CP16(dA + 16384 + so, bSrc + ko + s * 8, 16);
        }
    };

    // warp grid: 2 along M (64 rows each), 4 along N (32 cols each)
    const int mbase = (wid & 1) * 64, nbase = (wid >> 1) * 32;
    const int q = lid >> 3, rr = lid & 7;

    auto compute = [&](int st) {
        const uint32_t aT = sb + st * STAGE_BYTES;
        const uint32_t bT = aT + 16384;
#pragma unroll
        for (int ks = 0; ks < 4; ks++) {
            uint32_t ah[4][4];
#pragma unroll
            for (int mt = 0; mt < 4; mt++) {
                int row = mbase + mt * 16 + (q & 1) * 8 + rr;
                int ch  = 2 * ks + (q >> 1);
                LDSM4(ah[mt], aT + row * 128 + ((ch ^ (row & 7)) << 4));
            }
#pragma unroll
            for (int p = 0; p < 2; p++) {
                uint32_t bh[4];
                int nrow = nbase + p * 16 + (q >> 1) * 8 + rr;
                int ch   = 2 * ks + (q & 1);
                LDSM4(bh, bT + (uint32_t)(nrow * 128 + ((ch ^ (nrow & 7)) << 4)));
#pragma unroll
                for (int mt = 0; mt < 4; mt++)
#pragma unroll
                    for (int j = 0; j < 2; j++)
                        MMA16816(acc[mt][2 * p + j], ah[mt], bh[2 * j], bh[2 * j + 1]);
            }
        }
    };

    issue(0); CP_COMMIT();
    issue(1); CP_COMMIT();

#pragma unroll 1
    for (int c = 0; c < 8; c++) {
        CP_WAIT1();            // stage c resident
        __syncthreads();       // all warps done with stage (c-1)%3 reads
        if (c + 2 < 8) issue(c + 2);   // writes stage (c+2)%3 == (c-1)%3
        CP_COMMIT();           // uniform group count (may be empty)
        compute(c % NSTAGE);
    }

    // epilogue: half((acc + bias) * rsd)
#pragma unroll
    for (int mt = 0; mt < 4; mt++)
#pragma unroll
        for (int half = 0; half < 2; half++) {
            int row = m0 + mbase + mt * 16 + (lid >> 2) + half * 8;
            if (row < NN) {
                float rs = g_rsd[row];
#pragma unroll
                for (int nt = 0; nt < 4; nt++) {
                    int colrel = nbase + nt * 8 + (lid & 3) * 2;
                    __half2 hv = __floats2half2_rn(
                        (acc[mt][nt][half * 2 + 0] + biasS[colrel + 0]) * rs,
                        (acc[mt][nt][half * 2 + 1] + biasS[colrel + 1]) * rs);
                    *(uint32_t*)(Ch + (size_t)row * D + n0 + colrel) = *(uint32_t*)&hv;
                }
            }
        }
}

// accumulate 8 halves (uint4) into 8 floats
static __device__ __forceinline__ void addh8(float* a, uint4 v) {
    const uint32_t w[4] = {v.x, v.y, v.z, v.w};
#pragma unroll
    for (int i = 0; i < 4; i++) {
        __half2 p = *reinterpret_cast<const __half2*>(&w[i]);
        a[2 * i]     += __low2float(p);
        a[2 * i + 1] += __high2float(p);
    }
}

// ---------- aggregation + ELU on fp16 h. 4 nodes per 256-thread block,
// 64 threads per node, uint4 (16B) lanes. ----------
__global__ void agg_half_kernel(const __half* __restrict__ h,
                                const int* __restrict__ ei,
                                __half* __restrict__ hi) {
    const size_t node = (size_t)blockIdx.x * 4 + (threadIdx.x >> 6);
    const int t = threadIdx.x & 63;   // 16B lane within node
    const uint4* hv = (const uint4*)h;

    float a[8] = {0.f, 0.f, 0.f, 0.f, 0.f, 0.f, 0.f, 0.f};
    addh8(a, hv[node * 64 + t]);
    int e0 = ei[node * 3 + 0];
    int e1 = ei[node * 3 + 1];
    int e2 = ei[node * 3 + 2];
    if (e0 >= 0) addh8(a, hv[(size_t)e0 * 64 + t]);
    if (e1 >= 0) addh8(a, hv[(size_t)e1 * 64 + t]);
    if (e2 >= 0) addh8(a, hv[(size_t)e2 * 64 + t]);

    const float rs = g_rsd[node];
    __half2 o[4];
#pragma unroll
    for (int i = 0; i < 4; i++) {
        float x0 = a[2 * i] * rs, x1 = a[2 * i + 1] * rs;
        x0 = x0 > 0.f ? x0 : expm1f(x0);
        x1 = x1 > 0.f ? x1 : expm1f(x1);
        o[i] = __floats2half2_rn(x0, x1);
    }
    ((uint4*)hi)[node * 64 + t] = make_uint4(
        *(uint32_t*)&o[0], *(uint32_t*)&o[1], *(uint32_t*)&o[2], *(uint32_t*)&o[3]);
}

__global__ void agg_final_kernel(const __half* __restrict__ h,
                                 const int* __restrict__ ei,
                                 float* __restrict__ out) {
    const size_t node = (size_t)blockIdx.x * 4 + (threadIdx.x >> 6);
    const int t = threadIdx.x & 63;
    const uint4* hv = (const uint4*)h;

    float a[8] = {0.f, 0.f, 0.f, 0.f, 0.f, 0.f, 0.f, 0.f};
    addh8(a, hv[node * 64 + t]);
    int e0 = ei[node * 3 + 0];
    int e1 = ei[node * 3 + 1];
    int e2 = ei[node * 3 + 2];
    if (e0 >= 0) addh8(a, hv[(size_t)e0 * 64 + t]);
    if (e1 >= 0) addh8(a, hv[(size_t)e1 * 64 + t]);
    if (e2 >= 0) addh8(a, hv[(size_t)e2 * 64 + t]);

    const float rs = g_rsd[node];
    float o[8];
#pragma unroll
    for (int i = 0; i < 8; i++) {
        float x = a[i] * rs;
        o[i] = x > 0.f ? x : expm1f(x);
    }
    ((float4*)out)[node * 128 + 2 * t]     = make_float4(o[0], o[1], o[2], o[3]);
    ((float4*)out)[node * 128 + 2 * t + 1] = make_float4(o[4], o[5], o[6], o[7]);
}

extern "C" void kernel_launch(void* const* d_in, const int* in_sizes, int n_in,
                              void* d_out, int out_size) {
    const float* x  = nullptr;
    const int*   ei = nullptr;
    const float* Wt[2] = {nullptr, nullptr};
    const float* bt[2] = {nullptr, nullptr};
    int wi = 0, bi = 0;
    for (int i = 0; i < n_in; i++) {
        int sz = in_sizes[i];
        if (sz == NN * D)      x = (const float*)d_in[i];
        else if (sz == NN * 3) ei = (const int*)d_in[i];
        else if (sz == D * D)  { if (wi < 2) Wt[wi++] = (const float*)d_in[i]; }
        else if (sz == D)      { if (bi < 2) bt[bi++] = (const float*)d_in[i]; }
    }
    float* out = (float*)d_out;

    void *ph, *pah, *pw1, *pw2;
    cudaGetSymbolAddress(&ph,  g_h);
    cudaGetSymbolAddress(&pah, g_ahi);
    cudaGetSymbolAddress(&pw1, g_w1);
    cudaGetSymbolAddress(&pw2, g_w2);
    __half* hbuf = (__half*)ph;
    __half* ahi = (__half*)pah;
    __half *w1 = (__half*)pw1, *w2 = (__half*)pw2;

    cudaFuncSetAttribute(gemm_hmma, cudaFuncAttributeMaxDynamicSharedMemorySize, SMEM_TOTAL);

    deg_kernel<<<(NN + 255) / 256, 256>>>(ei);
    tohalf_kernel<<<(NN * D / 8 + 255) / 256, 256>>>(x, ahi, NN * D / 8);
    tohalf_kernel<<<(D * D / 8 + 255) / 256, 256>>>(Wt[0], w1, D * D / 8);
    tohalf_kernel<<<(D * D / 8 + 255) / 256, 256>>>(Wt[1], w2, D * D / 8);

    dim3 ggrid(D / 128, (NN + 127) / 128);  // (4, 782)
    gemm_hmma<<<ggrid, 256, SMEM_TOTAL>>>(ahi, w1, bt[0], hbuf);
    agg_half_kernel<<<NN / 4, 256>>>(hbuf, ei, ahi);
    gemm_hmma<<<ggrid, 256, SMEM_TOTAL>>>(ahi, w2, bt[1], hbuf);
    agg_final_kernel<<<NN / 4, 256>>>(hbuf, ei, out);
}